// round 2
// baseline (speedup 1.0000x reference)
#include <cuda_runtime.h>
#include <cstdint>

// Problem dims (fixed by the reference)
#define M_DIM 8192
#define N_DIM 1000
#define D_DIM 12288
#define KW    384          // D_DIM / 32 packed words per row

// Scratch for packed sign bits (device globals: allocation-free, graph-safe)
__device__ uint32_t g_bitsA[(size_t)M_DIM * KW];   // 12.6 MB
__device__ uint32_t g_bitsW[(size_t)N_DIM * KW];   // 1.5 MB

// ---------------------------------------------------------------------------
// Pack fp32 -> sign bits. bit = (x > 0). Each warp packs 4 words (128 floats)
// with lane-coalesced loads; ballot result is warp-uniform so lane 0 does one
// 16B store.
// ---------------------------------------------------------------------------
__global__ void pack_sign_kernel(const float* __restrict__ in,
                                 uint32_t* __restrict__ out,
                                 int nwords /* multiple of 4 */) {
    int warp_id = (blockIdx.x * blockDim.x + threadIdx.x) >> 5;
    int lane    = threadIdx.x & 31;
    int w0 = warp_id * 4;
    if (w0 >= nwords) return;
    const float* base = in + (size_t)w0 * 32;
    uint32_t w[4];
#pragma unroll
    for (int c = 0; c < 4; c++) {
        float x = base[c * 32 + lane];
        w[c] = __ballot_sync(0xffffffffu, x > 0.0f);
    }
    if (lane == 0) {
        *reinterpret_cast<uint4*>(out + w0) = make_uint4(w[0], w[1], w[2], w[3]);
    }
}

// ---------------------------------------------------------------------------
// Binary GEMM: out[m][n] = D - 2 * popc_sum(A_bits[m] ^ W_bits[n])
// 128x128 tile per CTA, 256 threads, 8x8 micro-tile per thread.
// Thread (tx,ty): rows m = mBase + ty + 16*i, cols n = nBase + tx + 16*j.
// Smem rows padded to 36 words -> uint4 LDS is 16B aligned; B-row addresses
// across the 16 tx lanes have bank = (36*tx) % 32-ish per 8-lane phase:
// stride 36 words means within each LDS.128 phase of 8 lanes banks are
// distinct -> conflict-free.
// ---------------------------------------------------------------------------
__global__ __launch_bounds__(256)
void bgemm_popc_kernel(const uint32_t* __restrict__ Ab,
                       const uint32_t* __restrict__ Wb,
                       float* __restrict__ out) {
    __shared__ uint32_t sA[128][36];
    __shared__ uint32_t sB[128][36];

    const int tid = threadIdx.x;
    const int tx  = tid & 15;
    const int ty  = tid >> 4;
    const int mBase = blockIdx.y * 128;
    const int nBase = blockIdx.x * 128;

    int acc[8][8];
#pragma unroll
    for (int i = 0; i < 8; i++)
#pragma unroll
        for (int j = 0; j < 8; j++) acc[i][j] = 0;

    for (int k0 = 0; k0 < KW; k0 += 32) {
        // Load 128 rows x 32 words for A and B tiles. 1024 uint4 total, 4 per thread.
#pragma unroll
        for (int l = 0; l < 4; l++) {
            int idx = tid + l * 256;      // 0..1023
            int row = idx >> 3;           // 8 uint4 per row
            int c4  = idx & 7;
            uint4 va = *reinterpret_cast<const uint4*>(
                Ab + (size_t)(mBase + row) * KW + k0 + c4 * 4);
            *reinterpret_cast<uint4*>(&sA[row][c4 * 4]) = va;

            int brow = nBase + row;
            uint4 vb = make_uint4(0u, 0u, 0u, 0u);
            if (brow < N_DIM) {
                vb = *reinterpret_cast<const uint4*>(
                    Wb + (size_t)brow * KW + k0 + c4 * 4);
            }
            *reinterpret_cast<uint4*>(&sB[row][c4 * 4]) = vb;
        }
        __syncthreads();

#pragma unroll
        for (int k = 0; k < 32; k += 4) {
            uint4 b4[8];
#pragma unroll
            for (int j = 0; j < 8; j++) {
                b4[j] = *reinterpret_cast<const uint4*>(&sB[tx + 16 * j][k]);
            }
#pragma unroll
            for (int i = 0; i < 8; i++) {
                uint4 a4 = *reinterpret_cast<const uint4*>(&sA[ty + 16 * i][k]);
#pragma unroll
                for (int j = 0; j < 8; j++) {
                    acc[i][j] += __popc(a4.x ^ b4[j].x) + __popc(a4.y ^ b4[j].y)
                               + __popc(a4.z ^ b4[j].z) + __popc(a4.w ^ b4[j].w);
                }
            }
        }
        __syncthreads();
    }

    // Epilogue: dot = D - 2*mismatches
#pragma unroll
    for (int i = 0; i < 8; i++) {
        int m = mBase + ty + 16 * i;
#pragma unroll
        for (int j = 0; j < 8; j++) {
            int n = nBase + tx + 16 * j;
            if (n < N_DIM) {
                out[(size_t)m * N_DIM + n] = (float)(D_DIM - 2 * acc[i][j]);
            }
        }
    }
}

// ---------------------------------------------------------------------------
extern "C" void kernel_launch(void* const* d_in, const int* in_sizes, int n_in,
                              void* d_out, int out_size) {
    const float* inp = (const float*)d_in[0];   // [8192, 12288]
    const float* wt  = (const float*)d_in[1];   // [1000, 12288]
    float* out = (float*)d_out;                 // [8192, 1000]

    uint32_t* bitsA = nullptr;
    uint32_t* bitsW = nullptr;
    cudaGetSymbolAddress((void**)&bitsA, g_bitsA);
    cudaGetSymbolAddress((void**)&bitsW, g_bitsW);

    // Pack input: 8192*384 = 3,145,728 words (4 per warp)
    {
        int nwords = M_DIM * KW;
        int warps = nwords / 4;
        int threads = 256;
        int blocks = (warps * 32 + threads - 1) / threads;
        pack_sign_kernel<<<blocks, threads>>>(inp, bitsA, nwords);
    }
    // Pack weight: 1000*384 = 384,000 words
    {
        int nwords = N_DIM * KW;
        int warps = nwords / 4;
        int threads = 256;
        int blocks = (warps * 32 + threads - 1) / threads;
        pack_sign_kernel<<<blocks, threads>>>(wt, bitsW, nwords);
    }
    // Binary GEMM: grid 8 (N tiles) x 64 (M tiles)
    {
        dim3 grid((N_DIM + 127) / 128, M_DIM / 128);
        bgemm_popc_kernel<<<grid, 256>>>(bitsA, bitsW, out);
    }
}